// round 6
// baseline (speedup 1.0000x reference)
#include <cuda_runtime.h>
#include <math.h>

// Problem constants
#define kS 2048
#define kE 1024
#define kH 16
#define kD 64
#define kB 2
#define kM (kB * kS)   // 4096

// Scratch (device globals — no runtime allocation)
__device__ float g_Q[kB * kH * kS * kD];   // [B,H,S,D] after QKV gemm
__device__ float g_K[kB * kH * kS * kD];
__device__ float g_V[kB * kH * kS * kD];
__device__ float g_A[kM * kE];             // attention output, [B,S,E]

// ---------------------------------------------------------------------------
// GEMM (NT): C[m,n] = sum_k A[m,k] * W[n,k] + bias[n]
// 128x128 tile, BK=8, 256 threads, 8x8 per thread.
// QKV variant: blockIdx.z selects (W,b,out); epilogue permutes to [B,H,S,D].
// ---------------------------------------------------------------------------
__global__ __launch_bounds__(256) void gemm_qkv_kernel(
    const float* __restrict__ X,
    const float* __restrict__ Wq, const float* __restrict__ bq,
    const float* __restrict__ Wk, const float* __restrict__ bk,
    const float* __restrict__ Wv, const float* __restrict__ bv)
{
    __shared__ float As[8][132];
    __shared__ float Bs[8][132];

    const float* W; const float* bias; float* Out;
    if (blockIdx.z == 0)      { W = Wq; bias = bq; Out = g_Q; }
    else if (blockIdx.z == 1) { W = Wk; bias = bk; Out = g_K; }
    else                      { W = Wv; bias = bv; Out = g_V; }

    const int tid  = threadIdx.x;
    const int m0   = blockIdx.y * 128;
    const int n0   = blockIdx.x * 128;
    const int lrow = tid >> 1;
    const int lc4  = (tid & 1) * 4;

    const float* Ap = X + (m0 + lrow) * kE + lc4;
    const float* Wp = W + (n0 + lrow) * kE + lc4;

    float acc[8][8];
#pragma unroll
    for (int i = 0; i < 8; i++)
#pragma unroll
        for (int j = 0; j < 8; j++) acc[i][j] = 0.f;

    const int tm = (tid >> 4) * 8;
    const int tn = (tid & 15) * 8;

    float4 av = *(const float4*)(Ap);
    float4 wv = *(const float4*)(Wp);
    for (int k0 = 0; k0 < kE; k0 += 8) {
        As[lc4 + 0][lrow] = av.x; As[lc4 + 1][lrow] = av.y;
        As[lc4 + 2][lrow] = av.z; As[lc4 + 3][lrow] = av.w;
        Bs[lc4 + 0][lrow] = wv.x; Bs[lc4 + 1][lrow] = wv.y;
        Bs[lc4 + 2][lrow] = wv.z; Bs[lc4 + 3][lrow] = wv.w;
        __syncthreads();
        if (k0 + 8 < kE) {
            av = *(const float4*)(Ap + k0 + 8);
            wv = *(const float4*)(Wp + k0 + 8);
        }
#pragma unroll
        for (int kk = 0; kk < 8; kk++) {
            float4 a0 = *(const float4*)&As[kk][tm];
            float4 a1 = *(const float4*)&As[kk][tm + 4];
            float4 b0 = *(const float4*)&Bs[kk][tn];
            float4 b1 = *(const float4*)&Bs[kk][tn + 4];
            float a[8] = {a0.x, a0.y, a0.z, a0.w, a1.x, a1.y, a1.z, a1.w};
            float b[8] = {b0.x, b0.y, b0.z, b0.w, b1.x, b1.y, b1.z, b1.w};
#pragma unroll
            for (int i = 0; i < 8; i++)
#pragma unroll
                for (int j = 0; j < 8; j++)
                    acc[i][j] = fmaf(a[i], b[j], acc[i][j]);
        }
        __syncthreads();
    }

    // Permuted store: row m=(b,s), col n=(h,d)  ->  Out[b][h][s][d]
#pragma unroll
    for (int i = 0; i < 8; i++) {
        int m  = m0 + tm + i;
        int bb = m >> 11;
        int s  = m & (kS - 1);
#pragma unroll
        for (int j = 0; j < 8; j++) {
            int n = n0 + tn + j;
            int h = n >> 6;
            int d = n & 63;
            Out[(((bb * kH + h) * kS) + s) * kD + d] = acc[i][j] + bias[n];
        }
    }
}

// Output projection GEMM: C = g_A @ Wo^T + bo, plain [M,N] store into d_out
__global__ __launch_bounds__(256) void gemm_out_kernel(
    const float* __restrict__ W, const float* __restrict__ bias,
    float* __restrict__ C)
{
    __shared__ float As[8][132];
    __shared__ float Bs[8][132];

    const int tid  = threadIdx.x;
    const int m0   = blockIdx.y * 128;
    const int n0   = blockIdx.x * 128;
    const int lrow = tid >> 1;
    const int lc4  = (tid & 1) * 4;

    const float* Ap = g_A + (m0 + lrow) * kE + lc4;
    const float* Wp = W   + (n0 + lrow) * kE + lc4;

    float acc[8][8];
#pragma unroll
    for (int i = 0; i < 8; i++)
#pragma unroll
        for (int j = 0; j < 8; j++) acc[i][j] = 0.f;

    const int tm = (tid >> 4) * 8;
    const int tn = (tid & 15) * 8;

    float4 av = *(const float4*)(Ap);
    float4 wv = *(const float4*)(Wp);
    for (int k0 = 0; k0 < kE; k0 += 8) {
        As[lc4 + 0][lrow] = av.x; As[lc4 + 1][lrow] = av.y;
        As[lc4 + 2][lrow] = av.z; As[lc4 + 3][lrow] = av.w;
        Bs[lc4 + 0][lrow] = wv.x; Bs[lc4 + 1][lrow] = wv.y;
        Bs[lc4 + 2][lrow] = wv.z; Bs[lc4 + 3][lrow] = wv.w;
        __syncthreads();
        if (k0 + 8 < kE) {
            av = *(const float4*)(Ap + k0 + 8);
            wv = *(const float4*)(Wp + k0 + 8);
        }
#pragma unroll
        for (int kk = 0; kk < 8; kk++) {
            float4 a0 = *(const float4*)&As[kk][tm];
            float4 a1 = *(const float4*)&As[kk][tm + 4];
            float4 b0 = *(const float4*)&Bs[kk][tn];
            float4 b1 = *(const float4*)&Bs[kk][tn + 4];
            float a[8] = {a0.x, a0.y, a0.z, a0.w, a1.x, a1.y, a1.z, a1.w};
            float b[8] = {b0.x, b0.y, b0.z, b0.w, b1.x, b1.y, b1.z, b1.w};
#pragma unroll
            for (int i = 0; i < 8; i++)
#pragma unroll
                for (int j = 0; j < 8; j++)
                    acc[i][j] = fmaf(a[i], b[j], acc[i][j]);
        }
        __syncthreads();
    }

#pragma unroll
    for (int i = 0; i < 8; i++) {
        int m = m0 + tm + i;
        float4 r0, r1;
        r0.x = acc[i][0] + bias[n0 + tn + 0];
        r0.y = acc[i][1] + bias[n0 + tn + 1];
        r0.z = acc[i][2] + bias[n0 + tn + 2];
        r0.w = acc[i][3] + bias[n0 + tn + 3];
        r1.x = acc[i][4] + bias[n0 + tn + 4];
        r1.y = acc[i][5] + bias[n0 + tn + 5];
        r1.z = acc[i][6] + bias[n0 + tn + 6];
        r1.w = acc[i][7] + bias[n0 + tn + 7];
        *(float4*)(C + m * kE + n0 + tn)     = r0;
        *(float4*)(C + m * kE + n0 + tn + 4) = r1;
    }
}

// ---------------------------------------------------------------------------
// RoPE in-place on g_Q and g_K ([B,H,S,D]); each thread owns a (d, d+32) pair
// ---------------------------------------------------------------------------
__global__ void rope_kernel(const float* __restrict__ cosp,
                            const float* __restrict__ sinp)
{
    const int total = kB * kH * kS * (kD / 2);   // pairs per tensor
    int i = blockIdx.x * blockDim.x + threadIdx.x;
    float* buf = (i < total) ? g_Q : g_K;
    int idx = (i < total) ? i : (i - total);
    int dh  = idx & 31;
    int row = idx >> 5;              // (b*H+h)*S + s
    int s   = row & (kS - 1);
    int base = row * kD;
    float x1 = buf[base + dh];
    float x2 = buf[base + dh + 32];
    float c1 = cosp[s * kD + dh],      s1 = sinp[s * kD + dh];
    float c2 = cosp[s * kD + dh + 32], s2 = sinp[s * kD + dh + 32];
    buf[base + dh]      = x1 * c1 - x2 * s1;
    buf[base + dh + 32] = x2 * c2 + x1 * s2;
}

// ---------------------------------------------------------------------------
// Causal flash attention. Grid (S/64, H, B), 256 threads.
// Per row: 4 threads (quad). c-assignment c=4*c16+t; dd-assignment 4t+16*jj.
// Smem rows padded to 68 floats (stride mod 32 = 4 -> quad banks distinct).
// ---------------------------------------------------------------------------
__global__ __launch_bounds__(256) void attn_kernel()
{
    extern __shared__ float smf[];
    float* Qs = smf;                 // [64][68]
    float* Ks = smf + 64 * 68;
    float* Vs = smf + 2 * 64 * 68;
    float* Ps = smf + 3 * 64 * 68;

    const int tid = threadIdx.x;
    const int qt  = blockIdx.x;
    const int h   = blockIdx.y;
    const int bb  = blockIdx.z;
    const int qs  = qt * 64;

    const float* headQ = g_Q + ((bb * kH + h) * kS) * kD;
    const float* headK = g_K + ((bb * kH + h) * kS) * kD;
    const float* headV = g_V + ((bb * kH + h) * kS) * kD;

    {   // load Q tile (coalesced)
        const float* src = headQ + qs * kD;
        int row = tid >> 4;
        int c4  = (tid & 15) * 4;
#pragma unroll
        for (int it = 0; it < 4; it++)
            *(float4*)&Qs[(row + 16 * it) * 68 + c4] =
                *(const float4*)(src + (row + 16 * it) * kD + c4);
    }

    const int r = tid >> 2;
    const int t = tid & 3;
    float mrow = -1e30f, lsum = 0.f;
    float4 o0 = make_float4(0.f, 0.f, 0.f, 0.f);
    float4 o1 = o0, o2 = o0, o3 = o0;

    for (int j = 0; j <= qt; j++) {
        __syncthreads();   // previous tile fully consumed
        {
            const float* ksrc = headK + j * 64 * kD;
            const float* vsrc = headV + j * 64 * kD;
            int row = tid >> 4;
            int c4  = (tid & 15) * 4;
#pragma unroll
            for (int it = 0; it < 4; it++) {
                *(float4*)&Ks[(row + 16 * it) * 68 + c4] =
                    *(const float4*)(ksrc + (row + 16 * it) * kD + c4);
                *(float4*)&Vs[(row + 16 * it) * 68 + c4] =
                    *(const float4*)(vsrc + (row + 16 * it) * kD + c4);
            }
        }
        __syncthreads();

        // scores: sc[c16] = Q[r,:] . K[4*c16+t,:]
        float sc[16];
#pragma unroll
        for (int c = 0; c < 16; c++) sc[c] = 0.f;
#pragma unroll 4
        for (int d4 = 0; d4 < 16; d4++) {
            float4 qv = *(const float4*)&Qs[r * 68 + d4 * 4];
#pragma unroll
            for (int c16 = 0; c16 < 16; c16++) {
                float4 kv = *(const float4*)&Ks[(4 * c16 + t) * 68 + d4 * 4];
                sc[c16] += qv.x * kv.x + qv.y * kv.y + qv.z * kv.z + qv.w * kv.w;
            }
        }

        const bool diag = (j == qt);
        float tmax = -1e30f;
#pragma unroll
        for (int c16 = 0; c16 < 16; c16++) {
            float v = sc[c16] * 0.125f;                 // 1/sqrt(64)
            if (diag && (4 * c16 + t) > r) v = -1e30f;  // causal mask
            sc[c16] = v;
            tmax = fmaxf(tmax, v);
        }
        tmax = fmaxf(tmax, __shfl_xor_sync(0xffffffffu, tmax, 1));
        tmax = fmaxf(tmax, __shfl_xor_sync(0xffffffffu, tmax, 2));

        float mnew = fmaxf(mrow, tmax);
        float corr = __expf(mrow - mnew);
        float psum = 0.f;
#pragma unroll
        for (int c16 = 0; c16 < 16; c16++) {
            float p = __expf(sc[c16] - mnew);
            psum += p;
            Ps[r * 68 + 4 * c16 + t] = p;
        }
        psum += __shfl_xor_sync(0xffffffffu, psum, 1);
        psum += __shfl_xor_sync(0xffffffffu, psum, 2);
        lsum = lsum * corr + psum;
        mrow = mnew;

        o0.x *= corr; o0.y *= corr; o0.z *= corr; o0.w *= corr;
        o1.x *= corr; o1.y *= corr; o1.z *= corr; o1.w *= corr;
        o2.x *= corr; o2.y *= corr; o2.z *= corr; o2.w *= corr;
        o3.x *= corr; o3.y *= corr; o3.z *= corr; o3.w *= corr;
        __syncwarp();   // quad's P writes visible to quad's P reads

        // O[r, 4t+16jj+..] += sum_c P[r,c] * V[c, ...]
#pragma unroll 4
        for (int c = 0; c < 64; c++) {
            float p   = Ps[r * 68 + c];
            float4 v0 = *(const float4*)&Vs[c * 68 + 4 * t];
            float4 v1 = *(const float4*)&Vs[c * 68 + 4 * t + 16];
            float4 v2 = *(const float4*)&Vs[c * 68 + 4 * t + 32];
            float4 v3 = *(const float4*)&Vs[c * 68 + 4 * t + 48];
            o0.x = fmaf(p, v0.x, o0.x); o0.y = fmaf(p, v0.y, o0.y);
            o0.z = fmaf(p, v0.z, o0.z); o0.w = fmaf(p, v0.w, o0.w);
            o1.x = fmaf(p, v1.x, o1.x); o1.y = fmaf(p, v1.y, o1.y);
            o1.z = fmaf(p, v1.z, o1.z); o1.w = fmaf(p, v1.w, o1.w);
            o2.x = fmaf(p, v2.x, o2.x); o2.y = fmaf(p, v2.y, o2.y);
            o2.z = fmaf(p, v2.z, o2.z); o2.w = fmaf(p, v2.w, o2.w);
            o3.x = fmaf(p, v3.x, o3.x); o3.y = fmaf(p, v3.y, o3.y);
            o3.z = fmaf(p, v3.z, o3.z); o3.w = fmaf(p, v3.w, o3.w);
        }
    }

    float inv = 1.f / lsum;
    o0.x *= inv; o0.y *= inv; o0.z *= inv; o0.w *= inv;
    o1.x *= inv; o1.y *= inv; o1.z *= inv; o1.w *= inv;
    o2.x *= inv; o2.y *= inv; o2.z *= inv; o2.w *= inv;
    o3.x *= inv; o3.y *= inv; o3.z *= inv; o3.w *= inv;

    // write to [B,S,E]: e = h*64 + dd
    float* dst = g_A + ((bb * kS) + qs + r) * kE + h * kD;
    *(float4*)(dst + 4 * t)      = o0;
    *(float4*)(dst + 4 * t + 16) = o1;
    *(float4*)(dst + 4 * t + 32) = o2;
    *(float4*)(dst + 4 * t + 48) = o3;
}

// ---------------------------------------------------------------------------
extern "C" void kernel_launch(void* const* d_in, const int* in_sizes, int n_in,
                              void* d_out, int out_size)
{
    (void)in_sizes; (void)n_in; (void)out_size;
    const float* x    = (const float*)d_in[0];
    // d_in[1] = mask: causal tril, handled analytically
    const float* cosp = (const float*)d_in[2];
    const float* sinp = (const float*)d_in[3];
    const float* Wq   = (const float*)d_in[4];
    const float* bq   = (const float*)d_in[5];
    const float* Wk   = (const float*)d_in[6];
    const float* bk   = (const float*)d_in[7];
    const float* Wv   = (const float*)d_in[8];
    const float* bv   = (const float*)d_in[9];
    const float* Wo   = (const float*)d_in[10];
    const float* bo   = (const float*)d_in[11];
    float* out = (float*)d_out;

    // QKV projection (fused 3 GEMMs via grid.z), permuted store to [B,H,S,D]
    dim3 gq(kE / 128, kM / 128, 3);
    gemm_qkv_kernel<<<gq, 256>>>(x, Wq, bq, Wk, bk, Wv, bv);

    // RoPE in-place on Q and K
    const int rope_threads = 2 * kB * kH * kS * (kD / 2);   // 4,194,304
    rope_kernel<<<rope_threads / 256, 256>>>(cosp, sinp);

    // Flash attention (dynamic smem 4*64*68*4 = 69632 B)
    const int attn_smem = 4 * 64 * 68 * (int)sizeof(float);
    cudaFuncSetAttribute(attn_kernel,
                         cudaFuncAttributeMaxDynamicSharedMemorySize, attn_smem);
    attn_kernel<<<dim3(kS / 64, kH, kB), 256, attn_smem>>>();

    // Output projection -> d_out
    gemm_out_kernel<<<dim3(kE / 128, kM / 128), 256>>>(Wo, bo, out);
}

// round 17
// speedup vs baseline: 1.2755x; 1.2755x over previous
#include <cuda_runtime.h>
#include <cuda_bf16.h>
#include <math.h>

// Problem constants
#define kS 2048
#define kE 1024
#define kH 16
#define kD 64
#define kB 2
#define kM (kB * kS)   // 4096

// Scratch (device globals — no runtime allocation)
__device__ float g_Q[kB * kH * kS * kD];   // [B,H,S,D] after QKV gemm
__device__ float g_K[kB * kH * kS * kD];
__device__ float g_V[kB * kH * kS * kD];
__device__ float g_A[kM * kE];             // attention output, [B,S,E]

// ---------------------------------------------------------------------------
// GEMM (NT): C[m,n] = sum_k A[m,k] * W[n,k] + bias[n]
// 128x128 tile, BK=8, 256 threads, 8x8 per thread.
// QKV variant: blockIdx.z selects (W,b,out); epilogue permutes to [B,H,S,D].
// ---------------------------------------------------------------------------
__global__ __launch_bounds__(256) void gemm_qkv_kernel(
    const float* __restrict__ X,
    const float* __restrict__ Wq, const float* __restrict__ bq,
    const float* __restrict__ Wk, const float* __restrict__ bk,
    const float* __restrict__ Wv, const float* __restrict__ bv)
{
    __shared__ float As[8][132];
    __shared__ float Bs[8][132];

    const float* W; const float* bias; float* Out;
    if (blockIdx.z == 0)      { W = Wq; bias = bq; Out = g_Q; }
    else if (blockIdx.z == 1) { W = Wk; bias = bk; Out = g_K; }
    else                      { W = Wv; bias = bv; Out = g_V; }

    const int tid  = threadIdx.x;
    const int m0   = blockIdx.y * 128;
    const int n0   = blockIdx.x * 128;
    const int lrow = tid >> 1;
    const int lc4  = (tid & 1) * 4;

    const float* Ap = X + (m0 + lrow) * kE + lc4;
    const float* Wp = W + (n0 + lrow) * kE + lc4;

    float acc[8][8];
#pragma unroll
    for (int i = 0; i < 8; i++)
#pragma unroll
        for (int j = 0; j < 8; j++) acc[i][j] = 0.f;

    const int tm = (tid >> 4) * 8;
    const int tn = (tid & 15) * 8;

    float4 av = *(const float4*)(Ap);
    float4 wv = *(const float4*)(Wp);
    for (int k0 = 0; k0 < kE; k0 += 8) {
        As[lc4 + 0][lrow] = av.x; As[lc4 + 1][lrow] = av.y;
        As[lc4 + 2][lrow] = av.z; As[lc4 + 3][lrow] = av.w;
        Bs[lc4 + 0][lrow] = wv.x; Bs[lc4 + 1][lrow] = wv.y;
        Bs[lc4 + 2][lrow] = wv.z; Bs[lc4 + 3][lrow] = wv.w;
        __syncthreads();
        if (k0 + 8 < kE) {
            av = *(const float4*)(Ap + k0 + 8);
            wv = *(const float4*)(Wp + k0 + 8);
        }
#pragma unroll
        for (int kk = 0; kk < 8; kk++) {
            float4 a0 = *(const float4*)&As[kk][tm];
            float4 a1 = *(const float4*)&As[kk][tm + 4];
            float4 b0 = *(const float4*)&Bs[kk][tn];
            float4 b1 = *(const float4*)&Bs[kk][tn + 4];
            float a[8] = {a0.x, a0.y, a0.z, a0.w, a1.x, a1.y, a1.z, a1.w};
            float b[8] = {b0.x, b0.y, b0.z, b0.w, b1.x, b1.y, b1.z, b1.w};
#pragma unroll
            for (int i = 0; i < 8; i++)
#pragma unroll
                for (int j = 0; j < 8; j++)
                    acc[i][j] = fmaf(a[i], b[j], acc[i][j]);
        }
        __syncthreads();
    }

    // Permuted store: row m=(b,s), col n=(h,d)  ->  Out[b][h][s][d]
#pragma unroll
    for (int i = 0; i < 8; i++) {
        int m  = m0 + tm + i;
        int bb = m >> 11;
        int s  = m & (kS - 1);
#pragma unroll
        for (int j = 0; j < 8; j++) {
            int n = n0 + tn + j;
            int h = n >> 6;
            int d = n & 63;
            Out[(((bb * kH + h) * kS) + s) * kD + d] = acc[i][j] + bias[n];
        }
    }
}

// Output projection GEMM: C = g_A @ Wo^T + bo, plain [M,N] store into d_out
__global__ __launch_bounds__(256) void gemm_out_kernel(
    const float* __restrict__ W, const float* __restrict__ bias,
    float* __restrict__ C)
{
    __shared__ float As[8][132];
    __shared__ float Bs[8][132];

    const int tid  = threadIdx.x;
    const int m0   = blockIdx.y * 128;
    const int n0   = blockIdx.x * 128;
    const int lrow = tid >> 1;
    const int lc4  = (tid & 1) * 4;

    const float* Ap = g_A + (m0 + lrow) * kE + lc4;
    const float* Wp = W   + (n0 + lrow) * kE + lc4;

    float acc[8][8];
#pragma unroll
    for (int i = 0; i < 8; i++)
#pragma unroll
        for (int j = 0; j < 8; j++) acc[i][j] = 0.f;

    const int tm = (tid >> 4) * 8;
    const int tn = (tid & 15) * 8;

    float4 av = *(const float4*)(Ap);
    float4 wv = *(const float4*)(Wp);
    for (int k0 = 0; k0 < kE; k0 += 8) {
        As[lc4 + 0][lrow] = av.x; As[lc4 + 1][lrow] = av.y;
        As[lc4 + 2][lrow] = av.z; As[lc4 + 3][lrow] = av.w;
        Bs[lc4 + 0][lrow] = wv.x; Bs[lc4 + 1][lrow] = wv.y;
        Bs[lc4 + 2][lrow] = wv.z; Bs[lc4 + 3][lrow] = wv.w;
        __syncthreads();
        if (k0 + 8 < kE) {
            av = *(const float4*)(Ap + k0 + 8);
            wv = *(const float4*)(Wp + k0 + 8);
        }
#pragma unroll
        for (int kk = 0; kk < 8; kk++) {
            float4 a0 = *(const float4*)&As[kk][tm];
            float4 a1 = *(const float4*)&As[kk][tm + 4];
            float4 b0 = *(const float4*)&Bs[kk][tn];
            float4 b1 = *(const float4*)&Bs[kk][tn + 4];
            float a[8] = {a0.x, a0.y, a0.z, a0.w, a1.x, a1.y, a1.z, a1.w};
            float b[8] = {b0.x, b0.y, b0.z, b0.w, b1.x, b1.y, b1.z, b1.w};
#pragma unroll
            for (int i = 0; i < 8; i++)
#pragma unroll
                for (int j = 0; j < 8; j++)
                    acc[i][j] = fmaf(a[i], b[j], acc[i][j]);
        }
        __syncthreads();
    }

#pragma unroll
    for (int i = 0; i < 8; i++) {
        int m = m0 + tm + i;
        float4 r0, r1;
        r0.x = acc[i][0] + bias[n0 + tn + 0];
        r0.y = acc[i][1] + bias[n0 + tn + 1];
        r0.z = acc[i][2] + bias[n0 + tn + 2];
        r0.w = acc[i][3] + bias[n0 + tn + 3];
        r1.x = acc[i][4] + bias[n0 + tn + 4];
        r1.y = acc[i][5] + bias[n0 + tn + 5];
        r1.z = acc[i][6] + bias[n0 + tn + 6];
        r1.w = acc[i][7] + bias[n0 + tn + 7];
        *(float4*)(C + m * kE + n0 + tn)     = r0;
        *(float4*)(C + m * kE + n0 + tn + 4) = r1;
    }
}

// ---------------------------------------------------------------------------
// RoPE in-place on g_Q and g_K ([B,H,S,D]); each thread owns a (d, d+32) pair
// ---------------------------------------------------------------------------
__global__ void rope_kernel(const float* __restrict__ cosp,
                            const float* __restrict__ sinp)
{
    const int total = kB * kH * kS * (kD / 2);   // pairs per tensor
    int i = blockIdx.x * blockDim.x + threadIdx.x;
    float* buf = (i < total) ? g_Q : g_K;
    int idx = (i < total) ? i : (i - total);
    int dh  = idx & 31;
    int row = idx >> 5;              // (b*H+h)*S + s
    int s   = row & (kS - 1);
    int base = row * kD;
    float x1 = buf[base + dh];
    float x2 = buf[base + dh + 32];
    float c1 = cosp[s * kD + dh],      s1 = sinp[s * kD + dh];
    float c2 = cosp[s * kD + dh + 32], s2 = sinp[s * kD + dh + 32];
    buf[base + dh]      = x1 * c1 - x2 * s1;
    buf[base + dh + 32] = x2 * c2 + x1 * s2;
}

// ---------------------------------------------------------------------------
// Causal flash attention. Grid (S/128, H, B), 256 threads.
// Q tile = 128 rows; each thread owns TWO rows (r and r+64), 16 cols each,
// via its 4-thread quad (t = tid&3). K/V tiles = 64 rows. Pad-68 rows.
// ---------------------------------------------------------------------------
__global__ __launch_bounds__(256) void attn_kernel()
{
    extern __shared__ float smf[];
    float* Qs = smf;                 // [128][68]
    float* Ks = smf + 128 * 68;      // [64][68]
    float* Vs = smf + 192 * 68;      // [64][68]
    float* Ps = smf + 256 * 68;      // [128][68]

    const int tid = threadIdx.x;
    const int qt  = blockIdx.x;
    const int h   = blockIdx.y;
    const int bb  = blockIdx.z;
    const int qs  = qt * 128;

    const float* headQ = g_Q + ((bb * kH + h) * kS) * kD;
    const float* headK = g_K + ((bb * kH + h) * kS) * kD;
    const float* headV = g_V + ((bb * kH + h) * kS) * kD;

    {   // load Q tile (128 rows, coalesced)
        const float* src = headQ + qs * kD;
        int row = tid >> 4;
        int c4  = (tid & 15) * 4;
#pragma unroll
        for (int it = 0; it < 8; it++)
            *(float4*)&Qs[(row + 16 * it) * 68 + c4] =
                *(const float4*)(src + (row + 16 * it) * kD + c4);
    }

    const int r  = tid >> 2;
    const int t  = tid & 3;
    const int gA = qs + r;
    const int gB = qs + r + 64;
    float mA = -1e30f, lA = 0.f;
    float mB = -1e30f, lB = 0.f;
    float oA[16], oB[16];
#pragma unroll
    for (int q = 0; q < 16; q++) { oA[q] = 0.f; oB[q] = 0.f; }

    const int jmax = 2 * qt + 1;
    for (int j = 0; j <= jmax; j++) {
        __syncthreads();   // previous tile fully consumed
        {
            const float* ksrc = headK + j * 64 * kD;
            const float* vsrc = headV + j * 64 * kD;
            int row = tid >> 4;
            int c4  = (tid & 15) * 4;
#pragma unroll
            for (int it = 0; it < 4; it++) {
                *(float4*)&Ks[(row + 16 * it) * 68 + c4] =
                    *(const float4*)(ksrc + (row + 16 * it) * kD + c4);
                *(float4*)&Vs[(row + 16 * it) * 68 + c4] =
                    *(const float4*)(vsrc + (row + 16 * it) * kD + c4);
            }
        }
        __syncthreads();

        // scores for both rows: s*[c] = Q[row,:] . K[4*c+t,:]
        float sA[16], sB[16];
#pragma unroll
        for (int c = 0; c < 16; c++) { sA[c] = 0.f; sB[c] = 0.f; }
#pragma unroll 4
        for (int d4 = 0; d4 < 16; d4++) {
            float4 qa = *(const float4*)&Qs[r * 68 + d4 * 4];
            float4 qb = *(const float4*)&Qs[(r + 64) * 68 + d4 * 4];
#pragma unroll
            for (int c = 0; c < 16; c++) {
                float4 kv = *(const float4*)&Ks[(4 * c + t) * 68 + d4 * 4];
                sA[c] += qa.x * kv.x + qa.y * kv.y + qa.z * kv.z + qa.w * kv.w;
                sB[c] += qb.x * kv.x + qb.y * kv.y + qb.z * kv.z + qb.w * kv.w;
            }
        }

        const int kbase = j * 64;
        float txA = -1e30f, txB = -1e30f;
#pragma unroll
        for (int c = 0; c < 16; c++) {
            int kc = kbase + 4 * c + t;
            float va = sA[c] * 0.125f;                 // 1/sqrt(64)
            float vb = sB[c] * 0.125f;
            if (kc > gA) va = -1e30f;                  // causal mask
            if (kc > gB) vb = -1e30f;
            sA[c] = va; sB[c] = vb;
            txA = fmaxf(txA, va);
            txB = fmaxf(txB, vb);
        }
        txA = fmaxf(txA, __shfl_xor_sync(0xffffffffu, txA, 1));
        txA = fmaxf(txA, __shfl_xor_sync(0xffffffffu, txA, 2));
        txB = fmaxf(txB, __shfl_xor_sync(0xffffffffu, txB, 1));
        txB = fmaxf(txB, __shfl_xor_sync(0xffffffffu, txB, 2));

        float mnA = fmaxf(mA, txA);
        float mnB = fmaxf(mB, txB);
        float cA = __expf(mA - mnA);
        float cB = __expf(mB - mnB);
        float psA = 0.f, psB = 0.f;
#pragma unroll
        for (int c = 0; c < 16; c++) {
            float pa = __expf(sA[c] - mnA);
            float pb = __expf(sB[c] - mnB);
            psA += pa;
            psB += pb;
            Ps[r * 68 + 4 * c + t] = pa;
            Ps[(r + 64) * 68 + 4 * c + t] = pb;
        }
        psA += __shfl_xor_sync(0xffffffffu, psA, 1);
        psA += __shfl_xor_sync(0xffffffffu, psA, 2);
        psB += __shfl_xor_sync(0xffffffffu, psB, 1);
        psB += __shfl_xor_sync(0xffffffffu, psB, 2);
        lA = lA * cA + psA; mA = mnA;
        lB = lB * cB + psB; mB = mnB;

#pragma unroll
        for (int q = 0; q < 16; q++) { oA[q] *= cA; oB[q] *= cB; }
        __syncwarp();   // quad's P writes visible to quad's P reads

        // O[row, 4t+16jj+q] += sum_c P[row,c] * V[c, 4t+16jj+q]
#pragma unroll 2
        for (int c = 0; c < 64; c++) {
            float pa = Ps[r * 68 + c];
            float pb = Ps[(r + 64) * 68 + c];
            const float* vr = &Vs[c * 68 + 4 * t];
#pragma unroll
            for (int jj = 0; jj < 4; jj++) {
                float4 vv = *(const float4*)(vr + 16 * jj);
                oA[4 * jj + 0] = fmaf(pa, vv.x, oA[4 * jj + 0]);
                oA[4 * jj + 1] = fmaf(pa, vv.y, oA[4 * jj + 1]);
                oA[4 * jj + 2] = fmaf(pa, vv.z, oA[4 * jj + 2]);
                oA[4 * jj + 3] = fmaf(pa, vv.w, oA[4 * jj + 3]);
                oB[4 * jj + 0] = fmaf(pb, vv.x, oB[4 * jj + 0]);
                oB[4 * jj + 1] = fmaf(pb, vv.y, oB[4 * jj + 1]);
                oB[4 * jj + 2] = fmaf(pb, vv.z, oB[4 * jj + 2]);
                oB[4 * jj + 3] = fmaf(pb, vv.w, oB[4 * jj + 3]);
            }
        }
    }

    float iA = 1.f / lA;
    float iB = 1.f / lB;
    float* dA = g_A + ((bb * kS) + gA) * kE + h * kD + 4 * t;
    float* dB = g_A + ((bb * kS) + gB) * kE + h * kD + 4 * t;
#pragma unroll
    for (int jj = 0; jj < 4; jj++) {
        float4 ra = make_float4(oA[4 * jj] * iA, oA[4 * jj + 1] * iA,
                                oA[4 * jj + 2] * iA, oA[4 * jj + 3] * iA);
        float4 rb = make_float4(oB[4 * jj] * iB, oB[4 * jj + 1] * iB,
                                oB[4 * jj + 2] * iB, oB[4 * jj + 3] * iB);
        *(float4*)(dA + 16 * jj) = ra;
        *(float4*)(dB + 16 * jj) = rb;
    }
}

// ---------------------------------------------------------------------------
extern "C" void kernel_launch(void* const* d_in, const int* in_sizes, int n_in,
                              void* d_out, int out_size)
{
    (void)in_sizes; (void)n_in; (void)out_size;
    const float* x    = (const float*)d_in[0];
    // d_in[1] = mask: causal tril, handled analytically
    const float* cosp = (const float*)d_in[2];
    const float* sinp = (const float*)d_in[3];
    const float* Wq   = (const float*)d_in[4];
    const float* bq   = (const float*)d_in[5];
    const float* Wk   = (const float*)d_in[6];
    const float* bk   = (const float*)d_in[7];
    const float* Wv   = (const float*)d_in[8];
    const float* bv   = (const float*)d_in[9];
    const float* Wo   = (const float*)d_in[10];
    const float* bo   = (const float*)d_in[11];
    float* out = (float*)d_out;

    // QKV projection (fused 3 GEMMs via grid.z), permuted store to [B,H,S,D]
    dim3 gq(kE / 128, kM / 128, 3);
    gemm_qkv_kernel<<<gq, 256>>>(x, Wq, bq, Wk, bk, Wv, bv);

    // RoPE in-place on Q and K
    const int rope_threads = 2 * kB * kH * kS * (kD / 2);   // 4,194,304
    rope_kernel<<<rope_threads / 256, 256>>>(cosp, sinp);

    // Flash attention (dynamic smem 384*68*4 = 104448 B)
    const int attn_smem = 384 * 68 * (int)sizeof(float);
    cudaFuncSetAttribute(attn_kernel,
                         cudaFuncAttributeMaxDynamicSharedMemorySize, attn_smem);
    attn_kernel<<<dim3(kS / 128, kH, kB), 256, attn_smem>>>();

    // Output projection -> d_out
    gemm_out_kernel<<<dim3(kE / 128, kM / 128), 256>>>(Wo, bo, out);
}